// round 4
// baseline (speedup 1.0000x reference)
#include <cuda_runtime.h>

#define Dh 256
#define Qn 64
#define Pn 128
#define Bn 64
#define G4 1024

__device__ float d_ga [Qn*Bn*Dh];
__device__ float d_UP [Qn*Bn*G4];
__device__ float d_sp [Pn*Bn*Dh];
__device__ float d_ApP[Pn*Bn*G4];
__device__ float d_WbT [Dh*Dh];
__device__ float d_WhhP[Dh*G4];

__global__ void prep_wb(const float* __restrict__ Wb) {
    int i = blockIdx.x * 256 + threadIdx.x;
    int e = i >> 8, d = i & 255;
    d_WbT[i] = Wb[d * 256 + e];
}

__global__ void prep_whh(const float* __restrict__ Whh) {
    int i = blockIdx.x * 256 + threadIdx.x;
    int e = i >> 10, r = i & 1023;
    int d = r >> 2, g = r & 3;
    d_WhhP[i] = Whh[(g * 256 + d) * 256 + e];
}

// C[m,n] = sum_k A[m,k]*B[n,k] (+bias +bias2), 64x64x16 tiles, 128 threads.
__global__ void __launch_bounds__(128) gemm_nt(
    const float* __restrict__ A, const float* __restrict__ Bm, float* __restrict__ C,
    int K, int lda, int ldb, int ldc,
    long long aBS, long long bBS, long long cBS,
    const float* __restrict__ bias, const float* __restrict__ bias2, int pack)
{
    __shared__ __align__(16) float As[16][68];
    __shared__ __align__(16) float Bs[16][68];
    int tid = threadIdx.x;
    const float* Ab = A + blockIdx.z * aBS + (long long)blockIdx.y * 64 * lda;
    const float* Bb = Bm + blockIdx.z * bBS + (long long)blockIdx.x * 64 * ldb;
    float* Cb = C + blockIdx.z * cBS;
    int m0 = blockIdx.y * 64, n0 = blockIdx.x * 64;
    int lr = tid >> 2, lk = (tid & 3) << 2;
    int tr = tid & 15, tc = tid >> 4;

    float acc[4][8];
#pragma unroll
    for (int i = 0; i < 4; ++i)
#pragma unroll
        for (int j = 0; j < 8; ++j) acc[i][j] = 0.f;

    for (int k0 = 0; k0 < K; k0 += 16) {
        float4 a0 = *(const float4*)(Ab + (long long)lr        * lda + k0 + lk);
        float4 a1 = *(const float4*)(Ab + (long long)(lr + 32) * lda + k0 + lk);
        float4 b0 = *(const float4*)(Bb + (long long)lr        * ldb + k0 + lk);
        float4 b1 = *(const float4*)(Bb + (long long)(lr + 32) * ldb + k0 + lk);
        __syncthreads();
        As[lk+0][lr] = a0.x; As[lk+1][lr] = a0.y; As[lk+2][lr] = a0.z; As[lk+3][lr] = a0.w;
        As[lk+0][lr+32] = a1.x; As[lk+1][lr+32] = a1.y; As[lk+2][lr+32] = a1.z; As[lk+3][lr+32] = a1.w;
        Bs[lk+0][lr] = b0.x; Bs[lk+1][lr] = b0.y; Bs[lk+2][lr] = b0.z; Bs[lk+3][lr] = b0.w;
        Bs[lk+0][lr+32] = b1.x; Bs[lk+1][lr+32] = b1.y; Bs[lk+2][lr+32] = b1.z; Bs[lk+3][lr+32] = b1.w;
        __syncthreads();
#pragma unroll
        for (int kk = 0; kk < 16; ++kk) {
            float4 av  = *(const float4*)(&As[kk][tr * 4]);
            float4 bv0 = *(const float4*)(&Bs[kk][tc * 8]);
            float4 bv1 = *(const float4*)(&Bs[kk][tc * 8 + 4]);
            float am[4] = {av.x, av.y, av.z, av.w};
            float bm_[8] = {bv0.x, bv0.y, bv0.z, bv0.w, bv1.x, bv1.y, bv1.z, bv1.w};
#pragma unroll
            for (int i = 0; i < 4; ++i)
#pragma unroll
                for (int j = 0; j < 8; ++j)
                    acc[i][j] = fmaf(am[i], bm_[j], acc[i][j]);
        }
    }
#pragma unroll
    for (int i = 0; i < 4; ++i) {
        int m = m0 + tr * 4 + i;
#pragma unroll
        for (int j = 0; j < 8; ++j) {
            int n = n0 + tc * 8 + j;
            float v = acc[i][j];
            if (bias)  v += bias[n];
            if (bias2) v += bias2[n];
            long long ci = pack ? ((long long)m * ldc + ((n & 255) << 2) + (n >> 8))
                                : ((long long)m * ldc + n);
            Cb[ci] = v;
        }
    }
}

__device__ __forceinline__ float fsigm(float x) {
    return __fdividef(1.f, 1.f + __expf(-x));
}
__device__ __forceinline__ float ftanh(float x) {
    float ex = __expf(2.f * x);
    return 1.f - __fdividef(2.f, ex + 1.f);
}

// one CTA per batch chain
__global__ void __launch_bounds__(256) recur(
    const float* __restrict__ h0, const float* __restrict__ c0,
    const float* __restrict__ alpha_w, float* __restrict__ out)
{
    extern __shared__ float sm[];
    float* ga_s  = sm;                  // 16384
    float* U_s   = ga_s + 16384;        // 32768 (q<32)
    float* aw_s  = U_s + 32768;         // 256
    float* h_s   = aw_s + 256;          // 256
    float* sfull = h_s + 256;           // 256
    float* part  = sfull + 256;         // 1024
    float* logit = part + 1024;         // 64
    float* alp   = logit + 64;          // 64

    int b = blockIdx.x;
    int t = threadIdx.x;

    for (int i = t; i < 16384; i += 256) {
        int q = i >> 8, d = i & 255;
        ga_s[i] = d_ga[((q << 6) + b) * 256 + d];
    }
    for (int i = t; i < 32768; i += 256) {
        int q = i >> 10, o = i & 1023;
        U_s[i] = d_UP[((q << 6) + b) * 1024 + o];
    }
    aw_s[t] = alpha_w[t];
    h_s[t] = h0[b * 256 + t];
    float c = c0[b * 256 + t];
    __syncthreads();

    const float4* Wb4 = (const float4*)d_WbT;
    const float4* Us4 = (const float4*)U_s;
    const float4* Ug4 = (const float4*)d_UP;
    const float4* Wh4 = (const float4*)d_WhhP;
    const float4* Ap4 = (const float4*)d_ApP;
    float4* part4 = (float4*)part;

    for (int step = 0; step < Pn; ++step) {
        // A: part = h @ Wb^T (split over e in 4 quarters)
        {
            int dq = t & 63;
            int es = (t >> 6) << 6;
            float4 acc = make_float4(0.f, 0.f, 0.f, 0.f);
#pragma unroll 8
            for (int e = es; e < es + 64; ++e) {
                float hv = h_s[e];
                float4 wv = Wb4[e * 64 + dq];
                acc.x = fmaf(hv, wv.x, acc.x);
                acc.y = fmaf(hv, wv.y, acc.y);
                acc.z = fmaf(hv, wv.z, acc.z);
                acc.w = fmaf(hv, wv.w, acc.w);
            }
            part4[t] = acc;
        }
        __syncthreads();
        sfull[t] = d_sp[(step * 64 + b) * 256 + t]
                 + part[t] + part[256 + t] + part[512 + t] + part[768 + t];
        __syncthreads();

        // B: logits[q] = sum_d tanh(ga+s)*aw  (4 threads per q)
        {
            int q = t >> 2, ds = (t & 3) << 6;
            float acc = 0.f;
#pragma unroll 4
            for (int d = ds; d < ds + 64; ++d)
                acc = fmaf(ftanh(ga_s[q * 256 + d] + sfull[d]), aw_s[d], acc);
            acc += __shfl_xor_sync(0xffffffffu, acc, 1);
            acc += __shfl_xor_sync(0xffffffffu, acc, 2);
            if ((t & 3) == 0) logit[q] = acc;
        }
        __syncthreads();

        // softmax over 64 (warp 0)
        if (t < 32) {
            float l0 = logit[t], l1 = logit[t + 32];
            float m = fmaxf(l0, l1);
#pragma unroll
            for (int o = 16; o; o >>= 1) m = fmaxf(m, __shfl_xor_sync(0xffffffffu, m, o));
            float e0 = __expf(l0 - m), e1 = __expf(l1 - m);
            float s = e0 + e1;
#pragma unroll
            for (int o = 16; o; o >>= 1) s += __shfl_xor_sync(0xffffffffu, s, o);
            float inv = __fdividef(1.f, s);
            alp[t] = e0 * inv; alp[t + 32] = e1 * inv;
        }
        __syncthreads();

        // C: gates (packed float4 per d) = A_p + sum_q alp*U + h @ Whh^T
        float4 g4 = Ap4[(step * 64 + b) * 256 + t];
#pragma unroll 8
        for (int q = 0; q < 32; ++q) {
            float av = alp[q];
            float4 u = Us4[q * 256 + t];
            g4.x = fmaf(av, u.x, g4.x); g4.y = fmaf(av, u.y, g4.y);
            g4.z = fmaf(av, u.z, g4.z); g4.w = fmaf(av, u.w, g4.w);
        }
#pragma unroll 8
        for (int q = 32; q < 64; ++q) {
            float av = alp[q];
            float4 u = Ug4[((q << 6) + b) * 256 + t];
            g4.x = fmaf(av, u.x, g4.x); g4.y = fmaf(av, u.y, g4.y);
            g4.z = fmaf(av, u.z, g4.z); g4.w = fmaf(av, u.w, g4.w);
        }
#pragma unroll 8
        for (int e = 0; e < 256; ++e) {
            float hv = h_s[e];
            float4 w4 = Wh4[e * 256 + t];
            g4.x = fmaf(hv, w4.x, g4.x); g4.y = fmaf(hv, w4.y, g4.y);
            g4.z = fmaf(hv, w4.z, g4.z); g4.w = fmaf(hv, w4.w, g4.w);
        }
        float cn = fsigm(g4.y) * c + fsigm(g4.x) * ftanh(g4.z);
        float hn = fsigm(g4.w) * ftanh(cn);
        out[(step * 64 + b) * 256 + t] = hn;
        __syncthreads();
        h_s[t] = hn;
        c = cn;
        __syncthreads();
    }
}

extern "C" void kernel_launch(void* const* d_in, const int* in_sizes, int n_in,
                              void* d_out, int out_size) {
    (void)in_sizes; (void)n_in; (void)out_size;
    const float* H_p  = (const float*)d_in[0];
    const float* h_ri = (const float*)d_in[1];
    const float* H_q  = (const float*)d_in[2];
    const float* hid  = (const float*)d_in[3];
    const float* Wa   = (const float*)d_in[4];
    const float* ba   = (const float*)d_in[5];
    const float* Wb   = (const float*)d_in[6];
    const float* Wg   = (const float*)d_in[7];
    const float* aw   = (const float*)d_in[8];
    const float* Wih  = (const float*)d_in[10];
    const float* Whh  = (const float*)d_in[11];
    const float* bih  = (const float*)d_in[12];
    const float* bhh  = (const float*)d_in[13];
    float* out = (float*)d_out;

    float *ga, *up, *sp, *ap;
    cudaGetSymbolAddress((void**)&ga, d_ga);
    cudaGetSymbolAddress((void**)&up, d_UP);
    cudaGetSymbolAddress((void**)&sp, d_sp);
    cudaGetSymbolAddress((void**)&ap, d_ApP);

    prep_wb<<<256, 256>>>(Wb);
    prep_whh<<<1024, 256>>>(Whh);

    // ga = H_q @ Wg^T                 M=4096 N=256 K=512
    gemm_nt<<<dim3(4, 64, 1), 128>>>(H_q, Wg, ga, 512, 512, 512, 256,
                                     0, 0, 0, nullptr, nullptr, 0);
    // s_p = H_p @ Wa^T + ba           M=8192 N=256
    gemm_nt<<<dim3(4, 128, 1), 128>>>(H_p, Wa, sp, 512, 512, 512, 256,
                                      0, 0, 0, ba, nullptr, 0);
    // A_p = H_p @ Wih[:, :512]^T + b_ih + b_hh  (gate-packed)
    gemm_nt<<<dim3(16, 128, 1), 128>>>(H_p, Wih, ap, 512, 512, 33280, 1024,
                                       0, 0, 0, bih, bhh, 1);
    // U[q] = H_q[q] @ Wih[:, 512(q+1):512(q+2)]^T  (batched over q, gate-packed)
    gemm_nt<<<dim3(16, 1, 64), 128>>>(H_q, Wih + 512, up, 512, 512, 33280, 1024,
                                      64 * 512, 512, 64 * 1024, nullptr, nullptr, 1);

    static int smem_set = 0;
    const int SMEM = 51072 * 4;
    if (!smem_set) {
        cudaFuncSetAttribute(recur, cudaFuncAttributeMaxDynamicSharedMemorySize, SMEM);
        smem_set = 1;
    }
    recur<<<64, 256, SMEM>>>(h_ri, hid, aw, out);
}

// round 5
// speedup vs baseline: 1.2813x; 1.2813x over previous
#include <cuda_runtime.h>

#define Dh 256
#define Qn 64
#define Pn 128
#define Bn 64

// ---------------- scratch ----------------
__device__ float d_ga [Qn*Bn*Dh];      // [q][b][d]
__device__ float d_UP [Qn*Bn*4*Dh];    // [(q*64+b)*1024 + d*4+g]
__device__ float d_sp [Pn*Bn*Dh];      // [t][b][d] incl ba
__device__ float d_ApP[Pn*Bn*4*Dh];    // [(t*64+b)*1024 + d*4+g] incl b_ih+b_hh
__device__ float d_WbT [Dh*Dh];        // [e][d]
__device__ float d_WhhP[Dh*4*Dh];      // [e*1024 + d*4+g]

__global__ void prep_wb(const float* __restrict__ Wb) {
    int i = blockIdx.x * 256 + threadIdx.x;
    int e = i >> 8, d = i & 255;
    d_WbT[i] = Wb[d * 256 + e];
}
__global__ void prep_whh(const float* __restrict__ Whh) {
    int i = blockIdx.x * 256 + threadIdx.x;
    int e = i >> 10, r = i & 1023;
    int d = r >> 2, g = r & 3;
    d_WhhP[i] = Whh[(g * 256 + d) * 256 + e];
}

// C[m,n] = sum_k A[m,k]*B[n,k] (+bias +bias2), 64x64x16 tiles, 128 threads.
__global__ void __launch_bounds__(128) gemm_nt(
    const float* __restrict__ A, const float* __restrict__ Bm, float* __restrict__ C,
    int K, int lda, int ldb, int ldc,
    long long aBS, long long bBS, long long cBS,
    const float* __restrict__ bias, const float* __restrict__ bias2, int pack)
{
    __shared__ __align__(16) float As[16][68];
    __shared__ __align__(16) float Bs[16][68];
    int tid = threadIdx.x;
    const float* Ab = A + blockIdx.z * aBS + (long long)blockIdx.y * 64 * lda;
    const float* Bb = Bm + blockIdx.z * bBS + (long long)blockIdx.x * 64 * ldb;
    float* Cb = C + blockIdx.z * cBS;
    int m0 = blockIdx.y * 64, n0 = blockIdx.x * 64;
    int lr = tid >> 2, lk = (tid & 3) << 2;
    int tr = tid & 15, tc = tid >> 4;

    float acc[4][8];
#pragma unroll
    for (int i = 0; i < 4; ++i)
#pragma unroll
        for (int j = 0; j < 8; ++j) acc[i][j] = 0.f;

    for (int k0 = 0; k0 < K; k0 += 16) {
        float4 a0 = *(const float4*)(Ab + (long long)lr        * lda + k0 + lk);
        float4 a1 = *(const float4*)(Ab + (long long)(lr + 32) * lda + k0 + lk);
        float4 b0 = *(const float4*)(Bb + (long long)lr        * ldb + k0 + lk);
        float4 b1 = *(const float4*)(Bb + (long long)(lr + 32) * ldb + k0 + lk);
        __syncthreads();
        As[lk+0][lr] = a0.x; As[lk+1][lr] = a0.y; As[lk+2][lr] = a0.z; As[lk+3][lr] = a0.w;
        As[lk+0][lr+32] = a1.x; As[lk+1][lr+32] = a1.y; As[lk+2][lr+32] = a1.z; As[lk+3][lr+32] = a1.w;
        Bs[lk+0][lr] = b0.x; Bs[lk+1][lr] = b0.y; Bs[lk+2][lr] = b0.z; Bs[lk+3][lr] = b0.w;
        Bs[lk+0][lr+32] = b1.x; Bs[lk+1][lr+32] = b1.y; Bs[lk+2][lr+32] = b1.z; Bs[lk+3][lr+32] = b1.w;
        __syncthreads();
#pragma unroll
        for (int kk = 0; kk < 16; ++kk) {
            float4 av  = *(const float4*)(&As[kk][tr * 4]);
            float4 bv0 = *(const float4*)(&Bs[kk][tc * 8]);
            float4 bv1 = *(const float4*)(&Bs[kk][tc * 8 + 4]);
            float am[4] = {av.x, av.y, av.z, av.w};
            float bm_[8] = {bv0.x, bv0.y, bv0.z, bv0.w, bv1.x, bv1.y, bv1.z, bv1.w};
#pragma unroll
            for (int i = 0; i < 4; ++i)
#pragma unroll
                for (int j = 0; j < 8; ++j)
                    acc[i][j] = fmaf(am[i], bm_[j], acc[i][j]);
        }
    }
#pragma unroll
    for (int i = 0; i < 4; ++i) {
        int m = m0 + tr * 4 + i;
#pragma unroll
        for (int j = 0; j < 8; ++j) {
            int n = n0 + tc * 8 + j;
            float v = acc[i][j];
            if (bias)  v += bias[n];
            if (bias2) v += bias2[n];
            long long ci = pack ? ((long long)m * ldc + ((n & 255) << 2) + (n >> 8))
                                : ((long long)m * ldc + n);
            Cb[ci] = v;
        }
    }
}

__device__ __forceinline__ float fsigm(float x) {
    return __fdividef(1.f, 1.f + __expf(-x));
}
__device__ __forceinline__ float ftanh(float x) {
    float ex = __expf(2.f * x);
    return 1.f - __fdividef(2.f, ex + 1.f);
}
__device__ __forceinline__ unsigned smem_u32(const void* p) {
    return (unsigned)__cvta_generic_to_shared(p);
}
#define CLUSTER_SYNC() do { \
    asm volatile("barrier.cluster.arrive.aligned;" ::: "memory"); \
    asm volatile("barrier.cluster.wait.aligned;"   ::: "memory"); } while (0)

// smem floats: Whh 32768 | U 8192 | Wb 8192 | ga 2112 | h 512 | wpart 256 |
//              part4 1024 | plog 512 | alp 64 | sfull 32 | aw 32  = 53696 floats
#define RC_SMEM_FLOATS 53696
#define RC_SMEM_BYTES  (RC_SMEM_FLOATS * 4)

// cluster of 8 CTAs per chain; rank j owns h-dims [32j,32j+32)
__global__ void __launch_bounds__(256) recur_cl(
    const float* __restrict__ h0, const float* __restrict__ c0,
    const float* __restrict__ alpha_w, float* __restrict__ out)
{
    extern __shared__ __align__(16) float sm[];
    float* Whh_s = sm;                // [e][128] (float4 rows)
    float* U_s   = Whh_s + 32768;     // [q][128]
    float* Wb_s  = U_s + 8192;        // [e][32]
    float* ga_s  = Wb_s + 8192;       // [q][33] padded
    float* h_s   = ga_s + 2112;       // 2 x 256 (double buffer)
    float* wpart = h_s + 512;         // [w][32]
    float* part4f= wpart + 256;       // [w][32] float4
    float* plog  = part4f + 1024;     // [rank][64]
    float* alp   = plog + 512;        // 64
    float* sfull = alp + 64;          // 32
    float* aw_s  = sfull + 32;        // 32

    int t = threadIdx.x;
    int w = t >> 5, l = t & 31;
    unsigned rank;
    asm("mov.u32 %0, %%cluster_ctarank;" : "=r"(rank));
    int b = blockIdx.x >> 3;
    int j = (int)rank;
    int dbase = 32 * j;
    int oq0   = 32 * j;   // float4 index offset into packed-1024 (=128j floats)

    const float4* WhhP4 = (const float4*)d_WhhP;
    const float4* UP4   = (const float4*)d_UP;
    const float4* ApP4  = (const float4*)d_ApP;
    float4* Whh4 = (float4*)Whh_s;
    float4* U4   = (float4*)U_s;
    float4* part4= (float4*)part4f;

    // one-time fills (all smem-resident afterwards)
    for (int i = t; i < 256 * 32; i += 256)
        Whh4[i] = WhhP4[(i >> 5) * 256 + oq0 + (i & 31)];
    for (int i = t; i < 64 * 32; i += 256)
        U4[i] = UP4[(((i >> 5) << 6) + b) * 256 + oq0 + (i & 31)];
    for (int i = t; i < 256 * 32; i += 256)
        Wb_s[i] = d_WbT[(i >> 5) * 256 + dbase + (i & 31)];
    for (int i = t; i < 64 * 32; i += 256)
        ga_s[(i >> 5) * 33 + (i & 31)] = d_ga[(((i >> 5) << 6) + b) * 256 + dbase + (i & 31)];
    if (t < 32) aw_s[t] = alpha_w[dbase + t];
    h_s[t] = h0[b * 256 + t];                       // buffer 0
    float c = (t < 32) ? c0[b * 256 + dbase + t] : 0.f;
    __syncthreads();
    CLUSTER_SYNC();

    for (int step = 0; step < Pn; ++step) {
        float* hcur = h_s + ((step & 1) << 8);
        float* hnxt = h_s + (((step + 1) & 1) << 8);

        // phase1: Wb matvec partials (warp w: e in [32w,32w+32), lane l = out dim)
        {
            float acc = 0.f;
#pragma unroll
            for (int ee = 0; ee < 32; ++ee) {
                int e = (w << 5) + ee;
                acc = fmaf(hcur[e], Wb_s[(e << 5) + l], acc);
            }
            wpart[(w << 5) + l] = acc;
        }
        __syncthreads();
        if (t < 32) {
            float s = d_sp[((step << 6) + b) * 256 + dbase + t];
#pragma unroll
            for (int ww = 0; ww < 8; ++ww) s += wpart[(ww << 5) + t];
            sfull[t] = s;
        }
        __syncthreads();

        // phase2: partial logits over owned 32 dims (4 threads/q), all-to-all
        {
            int q = t >> 2, ir = (t & 3) << 3;
            float acc = 0.f;
#pragma unroll
            for (int ii = 0; ii < 8; ++ii) {
                int i = ir + ii;
                acc = fmaf(ftanh(ga_s[q * 33 + i] + sfull[i]), aw_s[i], acc);
            }
            acc += __shfl_xor_sync(0xffffffffu, acc, 1);
            acc += __shfl_xor_sync(0xffffffffu, acc, 2);
            if ((t & 3) == 0) {
                unsigned loff = smem_u32(plog + j * 64 + q);
#pragma unroll
                for (int k = 0; k < 8; ++k) {
                    unsigned ra;
                    asm volatile("mapa.shared::cluster.u32 %0, %1, %2;"
                                 : "=r"(ra) : "r"(loff), "r"(k));
                    asm volatile("st.shared::cluster.f32 [%0], %1;"
                                 :: "r"(ra), "f"(acc) : "memory");
                }
            }
        }
        CLUSTER_SYNC();

        // phase3: replicated softmax over 64 (warp 0)
        if (t < 32) {
            float l0 = 0.f, l1 = 0.f;
#pragma unroll
            for (int k2 = 0; k2 < 8; ++k2) {
                l0 += plog[k2 * 64 + t];
                l1 += plog[k2 * 64 + t + 32];
            }
            float m = fmaxf(l0, l1);
#pragma unroll
            for (int o = 16; o; o >>= 1) m = fmaxf(m, __shfl_xor_sync(0xffffffffu, m, o));
            float e0 = __expf(l0 - m), e1 = __expf(l1 - m);
            float s2 = e0 + e1;
#pragma unroll
            for (int o = 16; o; o >>= 1) s2 += __shfl_xor_sync(0xffffffffu, s2, o);
            float inv = __fdividef(1.f, s2);
            alp[t] = e0 * inv; alp[t + 32] = e1 * inv;
        }
        __syncthreads();

        // phase4: gate partials; lane l <-> gate-quad (d = dbase+l, 4 gates)
        {
            float4 acc = make_float4(0.f, 0.f, 0.f, 0.f);
#pragma unroll
            for (int qq = 0; qq < 8; ++qq) {
                int q = w + (qq << 3);
                float a = alp[q];
                float4 u = U4[(q << 5) + l];
                acc.x = fmaf(a, u.x, acc.x); acc.y = fmaf(a, u.y, acc.y);
                acc.z = fmaf(a, u.z, acc.z); acc.w = fmaf(a, u.w, acc.w);
            }
#pragma unroll
            for (int ee = 0; ee < 32; ++ee) {
                int e = (w << 5) + ee;
                float hv = hcur[e];
                float4 wv = Whh4[(e << 5) + l];
                acc.x = fmaf(hv, wv.x, acc.x); acc.y = fmaf(hv, wv.y, acc.y);
                acc.z = fmaf(hv, wv.z, acc.z); acc.w = fmaf(hv, wv.w, acc.w);
            }
            part4[(w << 5) + l] = acc;
        }
        __syncthreads();

        // phase5: final gates + LSTM cell + h broadcast (threads 0..31)
        if (t < 32) {
            float4 g = ApP4[((step << 6) + b) * 256 + oq0 + t];
#pragma unroll
            for (int ww = 0; ww < 8; ++ww) {
                float4 p = part4[(ww << 5) + t];
                g.x += p.x; g.y += p.y; g.z += p.z; g.w += p.w;
            }
            float cn = fsigm(g.y) * c + fsigm(g.x) * ftanh(g.z);
            float hn = fsigm(g.w) * ftanh(cn);
            c = cn;
            out[((step << 6) + b) * 256 + dbase + t] = hn;
            unsigned loff = smem_u32(hnxt + dbase + t);
#pragma unroll
            for (int k = 0; k < 8; ++k) {
                unsigned ra;
                asm volatile("mapa.shared::cluster.u32 %0, %1, %2;"
                             : "=r"(ra) : "r"(loff), "r"(k));
                asm volatile("st.shared::cluster.f32 [%0], %1;"
                             :: "r"(ra), "f"(hn) : "memory");
            }
        }
        CLUSTER_SYNC();
    }
}

extern "C" void kernel_launch(void* const* d_in, const int* in_sizes, int n_in,
                              void* d_out, int out_size) {
    (void)in_sizes; (void)n_in; (void)out_size;
    const float* H_p  = (const float*)d_in[0];
    const float* h_ri = (const float*)d_in[1];
    const float* H_q  = (const float*)d_in[2];
    const float* hid  = (const float*)d_in[3];
    const float* Wa   = (const float*)d_in[4];
    const float* ba   = (const float*)d_in[5];
    const float* Wb   = (const float*)d_in[6];
    const float* Wg   = (const float*)d_in[7];
    const float* aw   = (const float*)d_in[8];
    const float* Wih  = (const float*)d_in[10];
    const float* Whh  = (const float*)d_in[11];
    const float* bih  = (const float*)d_in[12];
    const float* bhh  = (const float*)d_in[13];
    float* out = (float*)d_out;

    float *ga, *up, *sp, *ap;
    cudaGetSymbolAddress((void**)&ga, d_ga);
    cudaGetSymbolAddress((void**)&up, d_UP);
    cudaGetSymbolAddress((void**)&sp, d_sp);
    cudaGetSymbolAddress((void**)&ap, d_ApP);

    prep_wb<<<256, 256>>>(Wb);
    prep_whh<<<1024, 256>>>(Whh);

    // ga = H_q @ Wg^T
    gemm_nt<<<dim3(4, 64, 1), 128>>>(H_q, Wg, ga, 512, 512, 512, 256,
                                     0, 0, 0, nullptr, nullptr, 0);
    // s_p = H_p @ Wa^T + ba
    gemm_nt<<<dim3(4, 128, 1), 128>>>(H_p, Wa, sp, 512, 512, 512, 256,
                                      0, 0, 0, ba, nullptr, 0);
    // A_p = H_p @ Wih[:, :512]^T + b_ih + b_hh (gate-packed)
    gemm_nt<<<dim3(16, 128, 1), 128>>>(H_p, Wih, ap, 512, 512, 33280, 1024,
                                       0, 0, 0, bih, bhh, 1);
    // U[q] = H_q[q] @ Wih[:, 512(q+1):512(q+2)]^T (batched over q, gate-packed)
    gemm_nt<<<dim3(16, 1, 64), 128>>>(H_q, Wih + 512, up, 512, 512, 33280, 1024,
                                      64 * 512, 512, 64 * 1024, nullptr, nullptr, 1);

    cudaFuncSetAttribute(recur_cl, cudaFuncAttributeMaxDynamicSharedMemorySize,
                         RC_SMEM_BYTES);
    cudaLaunchConfig_t cfg = {};
    cfg.gridDim = dim3(512, 1, 1);
    cfg.blockDim = dim3(256, 1, 1);
    cfg.dynamicSmemBytes = RC_SMEM_BYTES;
    cfg.stream = 0;
    cudaLaunchAttribute at[1];
    at[0].id = cudaLaunchAttributeClusterDimension;
    at[0].val.clusterDim.x = 8;
    at[0].val.clusterDim.y = 1;
    at[0].val.clusterDim.z = 1;
    cfg.attrs = at;
    cfg.numAttrs = 1;
    cudaLaunchKernelEx(&cfg, recur_cl, h_ri, hid, aw, out);
}

// round 6
// speedup vs baseline: 1.2839x; 1.0021x over previous
#include <cuda_runtime.h>

#define Dh 256
#define Qn 64
#define Pn 128
#define Bn 64

// ---------------- scratch ----------------
__device__ float d_ga [Qn*Bn*Dh];      // [q][b][d]
__device__ float d_UP [Qn*Bn*4*Dh];    // [(q*64+b)*1024 + d*4+g]
__device__ float d_sp [Pn*Bn*Dh];      // [t][b][d] incl ba
__device__ float d_ApP[Pn*Bn*4*Dh];    // [(t*64+b)*1024 + d*4+g] incl b_ih+b_hh
__device__ float d_WbT [Dh*Dh];        // [e][d]
__device__ float d_WhhP[Dh*4*Dh];      // [e*1024 + d*4+g]

__global__ void prep_wb(const float* __restrict__ Wb) {
    int i = blockIdx.x * 256 + threadIdx.x;
    int e = i >> 8, d = i & 255;
    d_WbT[i] = Wb[d * 256 + e];
}
__global__ void prep_whh(const float* __restrict__ Whh) {
    int i = blockIdx.x * 256 + threadIdx.x;
    int e = i >> 10, r = i & 1023;
    int d = r >> 2, g = r & 3;
    d_WhhP[i] = Whh[(g * 256 + d) * 256 + e];
}

// C[m,n] = sum_k A[m,k]*B[n,k] (+bias +bias2), 64x64x16 tiles, 128 threads.
__global__ void __launch_bounds__(128) gemm_nt(
    const float* __restrict__ A, const float* __restrict__ Bm, float* __restrict__ C,
    int K, int lda, int ldb, int ldc,
    long long aBS, long long bBS, long long cBS,
    const float* __restrict__ bias, const float* __restrict__ bias2, int pack)
{
    __shared__ __align__(16) float As[16][68];
    __shared__ __align__(16) float Bs[16][68];
    int tid = threadIdx.x;
    const float* Ab = A + blockIdx.z * aBS + (long long)blockIdx.y * 64 * lda;
    const float* Bb = Bm + blockIdx.z * bBS + (long long)blockIdx.x * 64 * ldb;
    float* Cb = C + blockIdx.z * cBS;
    int m0 = blockIdx.y * 64, n0 = blockIdx.x * 64;
    int lr = tid >> 2, lk = (tid & 3) << 2;
    int tr = tid & 15, tc = tid >> 4;

    float acc[4][8];
#pragma unroll
    for (int i = 0; i < 4; ++i)
#pragma unroll
        for (int j = 0; j < 8; ++j) acc[i][j] = 0.f;

    for (int k0 = 0; k0 < K; k0 += 16) {
        float4 a0 = *(const float4*)(Ab + (long long)lr        * lda + k0 + lk);
        float4 a1 = *(const float4*)(Ab + (long long)(lr + 32) * lda + k0 + lk);
        float4 b0 = *(const float4*)(Bb + (long long)lr        * ldb + k0 + lk);
        float4 b1 = *(const float4*)(Bb + (long long)(lr + 32) * ldb + k0 + lk);
        __syncthreads();
        As[lk+0][lr] = a0.x; As[lk+1][lr] = a0.y; As[lk+2][lr] = a0.z; As[lk+3][lr] = a0.w;
        As[lk+0][lr+32] = a1.x; As[lk+1][lr+32] = a1.y; As[lk+2][lr+32] = a1.z; As[lk+3][lr+32] = a1.w;
        Bs[lk+0][lr] = b0.x; Bs[lk+1][lr] = b0.y; Bs[lk+2][lr] = b0.z; Bs[lk+3][lr] = b0.w;
        Bs[lk+0][lr+32] = b1.x; Bs[lk+1][lr+32] = b1.y; Bs[lk+2][lr+32] = b1.z; Bs[lk+3][lr+32] = b1.w;
        __syncthreads();
#pragma unroll
        for (int kk = 0; kk < 16; ++kk) {
            float4 av  = *(const float4*)(&As[kk][tr * 4]);
            float4 bv0 = *(const float4*)(&Bs[kk][tc * 8]);
            float4 bv1 = *(const float4*)(&Bs[kk][tc * 8 + 4]);
            float am[4] = {av.x, av.y, av.z, av.w};
            float bm_[8] = {bv0.x, bv0.y, bv0.z, bv0.w, bv1.x, bv1.y, bv1.z, bv1.w};
#pragma unroll
            for (int i = 0; i < 4; ++i)
#pragma unroll
                for (int j = 0; j < 8; ++j)
                    acc[i][j] = fmaf(am[i], bm_[j], acc[i][j]);
        }
    }
#pragma unroll
    for (int i = 0; i < 4; ++i) {
        int m = m0 + tr * 4 + i;
#pragma unroll
        for (int j = 0; j < 8; ++j) {
            int n = n0 + tc * 8 + j;
            float v = acc[i][j];
            if (bias)  v += bias[n];
            if (bias2) v += bias2[n];
            long long ci = pack ? ((long long)m * ldc + ((n & 255) << 2) + (n >> 8))
                                : ((long long)m * ldc + n);
            Cb[ci] = v;
        }
    }
}

__device__ __forceinline__ float fsigm(float x) {
    return __fdividef(1.f, 1.f + __expf(-x));
}
__device__ __forceinline__ float ftanh(float x) {
    float ex = __expf(2.f * x);
    return 1.f - __fdividef(2.f, ex + 1.f);
}
__device__ __forceinline__ unsigned smem_u32(const void* p) {
    return (unsigned)__cvta_generic_to_shared(p);
}
#define CLUSTER_SYNC() do { \
    asm volatile("barrier.cluster.arrive.aligned;" ::: "memory"); \
    asm volatile("barrier.cluster.wait.aligned;"   ::: "memory"); } while (0)

// smem floats: Whh 32768 | U 8192 | Wb 8192 | ga 2112 | h 512 | wpart 256 |
//              part4 1024 | plog 512 | alp 64 | sfull 32 | aw 32  = 53696 floats
#define RC_SMEM_FLOATS 53696
#define RC_SMEM_BYTES  (RC_SMEM_FLOATS * 4)

// cluster of 8 CTAs per chain; rank j owns h-dims [32j,32j+32)
__global__ void __launch_bounds__(256) recur_cl(
    const float* __restrict__ h0, const float* __restrict__ c0,
    const float* __restrict__ alpha_w, float* __restrict__ out)
{
    extern __shared__ __align__(16) float sm[];
    float* Whh_s = sm;                // [e][128] (float4 rows)
    float* U_s   = Whh_s + 32768;     // [q][128]
    float* Wb_s  = U_s + 8192;        // [e][32]
    float* ga_s  = Wb_s + 8192;       // [q][33] padded
    float* h_s   = ga_s + 2112;       // 2 x 256 (double buffer)
    float* wpart = h_s + 512;         // [w][32]
    float* part4f= wpart + 256;       // [w][32] float4
    float* plog  = part4f + 1024;     // [rank][64]
    float* alp   = plog + 512;        // 64
    float* sfull = alp + 64;          // 32
    float* aw_s  = sfull + 32;        // 32

    int t = threadIdx.x;
    int w = t >> 5, l = t & 31;
    unsigned rank;
    asm("mov.u32 %0, %%cluster_ctarank;" : "=r"(rank));
    int b = blockIdx.x >> 3;
    int j = (int)rank;
    int dbase = 32 * j;
    int oq0   = 32 * j;   // float4 index offset into packed-1024 (=128j floats)

    const float4* WhhP4 = (const float4*)d_WhhP;
    const float4* UP4   = (const float4*)d_UP;
    const float4* ApP4  = (const float4*)d_ApP;
    float4* Whh4 = (float4*)Whh_s;
    float4* U4   = (float4*)U_s;
    float4* part4= (float4*)part4f;

    // one-time fills (all smem-resident afterwards)
    for (int i = t; i < 256 * 32; i += 256)
        Whh4[i] = WhhP4[(i >> 5) * 256 + oq0 + (i & 31)];
    for (int i = t; i < 64 * 32; i += 256)
        U4[i] = UP4[(((i >> 5) << 6) + b) * 256 + oq0 + (i & 31)];
    for (int i = t; i < 256 * 32; i += 256)
        Wb_s[i] = d_WbT[(i >> 5) * 256 + dbase + (i & 31)];
    for (int i = t; i < 64 * 32; i += 256)
        ga_s[(i >> 5) * 33 + (i & 31)] = d_ga[(((i >> 5) << 6) + b) * 256 + dbase + (i & 31)];
    if (t < 32) aw_s[t] = alpha_w[dbase + t];
    h_s[t] = h0[b * 256 + t];                       // buffer 0
    float c = (t < 32) ? c0[b * 256 + dbase + t] : 0.f;
    __syncthreads();
    CLUSTER_SYNC();

    for (int step = 0; step < Pn; ++step) {
        float* hcur = h_s + ((step & 1) << 8);
        float* hnxt = h_s + (((step + 1) & 1) << 8);

        // phase1: Wb matvec partials (warp w: e in [32w,32w+32), lane l = out dim)
        {
            float acc = 0.f;
#pragma unroll
            for (int ee = 0; ee < 32; ++ee) {
                int e = (w << 5) + ee;
                acc = fmaf(hcur[e], Wb_s[(e << 5) + l], acc);
            }
            wpart[(w << 5) + l] = acc;
        }
        __syncthreads();
        if (t < 32) {
            float s = d_sp[((step << 6) + b) * 256 + dbase + t];
#pragma unroll
            for (int ww = 0; ww < 8; ++ww) s += wpart[(ww << 5) + t];
            sfull[t] = s;
        }
        __syncthreads();

        // phase2: partial logits over owned 32 dims (4 threads/q), all-to-all
        {
            int q = t >> 2, ir = (t & 3) << 3;
            float acc = 0.f;
#pragma unroll
            for (int ii = 0; ii < 8; ++ii) {
                int i = ir + ii;
                acc = fmaf(ftanh(ga_s[q * 33 + i] + sfull[i]), aw_s[i], acc);
            }
            acc += __shfl_xor_sync(0xffffffffu, acc, 1);
            acc += __shfl_xor_sync(0xffffffffu, acc, 2);
            if ((t & 3) == 0) {
                unsigned loff = smem_u32(plog + j * 64 + q);
#pragma unroll
                for (int k = 0; k < 8; ++k) {
                    unsigned ra;
                    asm volatile("mapa.shared::cluster.u32 %0, %1, %2;"
                                 : "=r"(ra) : "r"(loff), "r"(k));
                    asm volatile("st.shared::cluster.f32 [%0], %1;"
                                 :: "r"(ra), "f"(acc) : "memory");
                }
            }
        }
        CLUSTER_SYNC();

        // phase3: replicated softmax over 64 (warp 0)
        if (t < 32) {
            float l0 = 0.f, l1 = 0.f;
#pragma unroll
            for (int k2 = 0; k2 < 8; ++k2) {
                l0 += plog[k2 * 64 + t];
                l1 += plog[k2 * 64 + t + 32];
            }
            float m = fmaxf(l0, l1);
#pragma unroll
            for (int o = 16; o; o >>= 1) m = fmaxf(m, __shfl_xor_sync(0xffffffffu, m, o));
            float e0 = __expf(l0 - m), e1 = __expf(l1 - m);
            float s2 = e0 + e1;
#pragma unroll
            for (int o = 16; o; o >>= 1) s2 += __shfl_xor_sync(0xffffffffu, s2, o);
            float inv = __fdividef(1.f, s2);
            alp[t] = e0 * inv; alp[t + 32] = e1 * inv;
        }
        __syncthreads();

        // phase4: gate partials; lane l <-> gate-quad (d = dbase+l, 4 gates)
        {
            float4 acc = make_float4(0.f, 0.f, 0.f, 0.f);
#pragma unroll
            for (int qq = 0; qq < 8; ++qq) {
                int q = w + (qq << 3);
                float a = alp[q];
                float4 u = U4[(q << 5) + l];
                acc.x = fmaf(a, u.x, acc.x); acc.y = fmaf(a, u.y, acc.y);
                acc.z = fmaf(a, u.z, acc.z); acc.w = fmaf(a, u.w, acc.w);
            }
#pragma unroll
            for (int ee = 0; ee < 32; ++ee) {
                int e = (w << 5) + ee;
                float hv = hcur[e];
                float4 wv = Whh4[(e << 5) + l];
                acc.x = fmaf(hv, wv.x, acc.x); acc.y = fmaf(hv, wv.y, acc.y);
                acc.z = fmaf(hv, wv.z, acc.z); acc.w = fmaf(hv, wv.w, acc.w);
            }
            part4[(w << 5) + l] = acc;
        }
        __syncthreads();

        // phase5: final gates + LSTM cell + h broadcast (threads 0..31)
        if (t < 32) {
            float4 g = ApP4[((step << 6) + b) * 256 + oq0 + t];
#pragma unroll
            for (int ww = 0; ww < 8; ++ww) {
                float4 p = part4[(ww << 5) + t];
                g.x += p.x; g.y += p.y; g.z += p.z; g.w += p.w;
            }
            float cn = fsigm(g.y) * c + fsigm(g.x) * ftanh(g.z);
            float hn = fsigm(g.w) * ftanh(cn);
            c = cn;
            out[((step << 6) + b) * 256 + dbase + t] = hn;
            unsigned loff = smem_u32(hnxt + dbase + t);
#pragma unroll
            for (int k = 0; k < 8; ++k) {
                unsigned ra;
                asm volatile("mapa.shared::cluster.u32 %0, %1, %2;"
                             : "=r"(ra) : "r"(loff), "r"(k));
                asm volatile("st.shared::cluster.f32 [%0], %1;"
                             :: "r"(ra), "f"(hn) : "memory");
            }
        }
        CLUSTER_SYNC();
    }
}

extern "C" void kernel_launch(void* const* d_in, const int* in_sizes, int n_in,
                              void* d_out, int out_size) {
    (void)in_sizes; (void)n_in; (void)out_size;
    const float* H_p  = (const float*)d_in[0];
    const float* h_ri = (const float*)d_in[1];
    const float* H_q  = (const float*)d_in[2];
    const float* hid  = (const float*)d_in[3];
    const float* Wa   = (const float*)d_in[4];
    const float* ba   = (const float*)d_in[5];
    const float* Wb   = (const float*)d_in[6];
    const float* Wg   = (const float*)d_in[7];
    const float* aw   = (const float*)d_in[8];
    const float* Wih  = (const float*)d_in[10];
    const float* Whh  = (const float*)d_in[11];
    const float* bih  = (const float*)d_in[12];
    const float* bhh  = (const float*)d_in[13];
    float* out = (float*)d_out;

    float *ga, *up, *sp, *ap;
    cudaGetSymbolAddress((void**)&ga, d_ga);
    cudaGetSymbolAddress((void**)&up, d_UP);
    cudaGetSymbolAddress((void**)&sp, d_sp);
    cudaGetSymbolAddress((void**)&ap, d_ApP);

    prep_wb<<<256, 256>>>(Wb);
    prep_whh<<<1024, 256>>>(Whh);

    // ga = H_q @ Wg^T
    gemm_nt<<<dim3(4, 64, 1), 128>>>(H_q, Wg, ga, 512, 512, 512, 256,
                                     0, 0, 0, nullptr, nullptr, 0);
    // s_p = H_p @ Wa^T + ba
    gemm_nt<<<dim3(4, 128, 1), 128>>>(H_p, Wa, sp, 512, 512, 512, 256,
                                      0, 0, 0, ba, nullptr, 0);
    // A_p = H_p @ Wih[:, :512]^T + b_ih + b_hh (gate-packed)
    gemm_nt<<<dim3(16, 128, 1), 128>>>(H_p, Wih, ap, 512, 512, 33280, 1024,
                                       0, 0, 0, bih, bhh, 1);
    // U[q] = H_q[q] @ Wih[:, 512(q+1):512(q+2)]^T (batched over q, gate-packed)
    gemm_nt<<<dim3(16, 1, 64), 128>>>(H_q, Wih + 512, up, 512, 512, 33280, 1024,
                                      64 * 512, 512, 64 * 1024, nullptr, nullptr, 1);

    cudaFuncSetAttribute(recur_cl, cudaFuncAttributeMaxDynamicSharedMemorySize,
                         RC_SMEM_BYTES);
    cudaLaunchConfig_t cfg = {};
    cfg.gridDim = dim3(512, 1, 1);
    cfg.blockDim = dim3(256, 1, 1);
    cfg.dynamicSmemBytes = RC_SMEM_BYTES;
    cfg.stream = 0;
    cudaLaunchAttribute at[1];
    at[0].id = cudaLaunchAttributeClusterDimension;
    at[0].val.clusterDim.x = 8;
    at[0].val.clusterDim.y = 1;
    at[0].val.clusterDim.z = 1;
    cfg.attrs = at;
    cfg.numAttrs = 1;
    cudaLaunchKernelEx(&cfg, recur_cl, h_ri, hid, aw, out);
}